// round 8
// baseline (speedup 1.0000x reference)
#include <cuda_runtime.h>
#include <cuda_bf16.h>
#include <cstdint>

// Problem: HyperLayer multilinear gather/scatter.
//   x            : [1024,1024] fp32
//   real_indices : [N=500000, 4] fp32  (r0,r1 -> input coords, r2,r3 -> output coords)
//   real_values  : [N] fp32
//   y (out)      : [1024,1024] fp32
//
// For each sample: over 2^4 floor/ceil combos, weight = prod(1-|int_k - r_k|),
// contrib = weight * val * x[i0,i1], scatter-add into y[o2,o3].
// Factorized: G = sum over (c0,c1) of w0*w1*x ; then 4 atomic adds with w2*w3.
// Weights use wf = 1-(r-floor), wc = 1-(ceil-r) per dim, exactly matching the
// reference (including the frac==0 double-count where floor==ceil and both
// weights are 1).

#define DIM 1024

__global__ void hyper_zero_kernel(float4* __restrict__ y, int n4) {
    int i = blockIdx.x * blockDim.x + threadIdx.x;
    if (i < n4) y[i] = make_float4(0.f, 0.f, 0.f, 0.f);
}

__global__ void __launch_bounds__(256) hyper_main_kernel(
    const float* __restrict__ x,
    const float4* __restrict__ ri,   // [N] of (r0,r1,r2,r3)
    const float* __restrict__ rv,    // [N]
    float* __restrict__ y,
    int N)
{
    int n = blockIdx.x * blockDim.x + threadIdx.x;
    if (n >= N) return;

    float4 r = ri[n];
    float v  = rv[n];

    // dim 0 (input row)
    float f0 = floorf(r.x), c0 = ceilf(r.x);
    float wf0 = 1.0f - (r.x - f0);
    float wc0 = 1.0f - (c0 - r.x);
    // dim 1 (input col)
    float f1 = floorf(r.y), c1 = ceilf(r.y);
    float wf1 = 1.0f - (r.y - f1);
    float wc1 = 1.0f - (c1 - r.y);
    // dim 2 (output row)
    float f2 = floorf(r.z), c2 = ceilf(r.z);
    float wf2 = 1.0f - (r.z - f2);
    float wc2 = 1.0f - (c2 - r.z);
    // dim 3 (output col)
    float f3 = floorf(r.w), c3 = ceilf(r.w);
    float wf3 = 1.0f - (r.w - f3);
    float wc3 = 1.0f - (c3 - r.w);

    int if0 = (int)f0, ic0 = (int)c0;
    int if1 = (int)f1, ic1 = (int)c1;
    int if2 = (int)f2, ic2 = (int)c2;
    int if3 = (int)f3, ic3 = (int)c3;

    const float* row_f = x + (long)if0 * DIM;
    const float* row_c = x + (long)ic0 * DIM;

    // Gather: bilinear-style sum over input combos (4 scattered L2-resident loads)
    float G = wf0 * (wf1 * __ldg(&row_f[if1]) + wc1 * __ldg(&row_f[ic1]))
            + wc0 * (wf1 * __ldg(&row_c[if1]) + wc1 * __ldg(&row_c[ic1]));

    float gv = G * v;

    // Scatter: 4 atomic adds over output combos
    float* yrf = y + (long)if2 * DIM;
    float* yrc = y + (long)ic2 * DIM;
    atomicAdd(&yrf[if3], gv * wf2 * wf3);
    atomicAdd(&yrf[ic3], gv * wf2 * wc3);
    atomicAdd(&yrc[if3], gv * wc2 * wf3);
    atomicAdd(&yrc[ic3], gv * wc2 * wc3);
}

extern "C" void kernel_launch(void* const* d_in, const int* in_sizes, int n_in,
                              void* d_out, int out_size) {
    const float*  x  = (const float*)d_in[0];        // 1024*1024
    const float4* ri = (const float4*)d_in[1];       // N*4 floats, 16B-aligned per sample
    const float*  rv = (const float*)d_in[2];        // N
    float*        y  = (float*)d_out;                // 1024*1024

    int N = in_sizes[2];

    // Zero output (poisoned to 0xAA by harness)
    int n4 = out_size / 4;
    hyper_zero_kernel<<<(n4 + 255) / 256, 256>>>((float4*)y, n4);

    hyper_main_kernel<<<(N + 255) / 256, 256>>>(x, ri, rv, y, N);
}

// round 11
// speedup vs baseline: 1.0657x; 1.0657x over previous
#include <cuda_runtime.h>
#include <cuda_bf16.h>
#include <cstdint>

// HyperLayer multilinear gather/scatter, factorized:
//   G = bilinear gather from x over (dim0,dim1); y[o2,o3] += v*G*w2*w3 over 4 combos.
// L1tex-wavefront bound (divergent gathers + atomics). Fuse adjacent-column
// pairs into float2 ops when the floor col index is even; 2 samples/thread
// for MLP. R10 fix: guard on tid < T (overflow threads of the rounded-up grid
// were double-processing 112 samples).

#define DIM 1024

__global__ void hyper_zero_kernel(float4* __restrict__ y, int n4) {
    int i = blockIdx.x * blockDim.x + threadIdx.x;
    if (i < n4) y[i] = make_float4(0.f, 0.f, 0.f, 0.f);
}

// Gather x[base+i], x[base+j] where j==i or j==i+1 (floor/ceil of same coord).
__device__ __forceinline__ void gather_pair(const float* __restrict__ base,
                                            int i, int j, float& a, float& b) {
    if (((i & 1) == 0) && (j == i + 1)) {
        float2 p = __ldg((const float2*)(base + i));
        a = p.x; b = p.y;
    } else {
        a = __ldg(base + i);
        b = (j == i) ? a : __ldg(base + j);
    }
}

// Scatter-add va -> base[i], vb -> base[j] (j==i or j==i+1).
__device__ __forceinline__ void scatter_pair(float* __restrict__ base,
                                             int i, int j, float va, float vb) {
    if (((i & 1) == 0) && (j == i + 1)) {
        atomicAdd((float2*)(base + i), make_float2(va, vb));
    } else {
        // j==i case: two adds to the same address == reference double-count.
        atomicAdd(base + i, va);
        atomicAdd(base + j, vb);
    }
}

__device__ __forceinline__ void process_sample(const float* __restrict__ x,
                                               float4 r, float v,
                                               float* __restrict__ y) {
    // wf = 1-(r-floor), wc = 1-(ceil-r); matches reference including the
    // frac==0 double-count (floor==ceil, both weights 1).
    float f0 = floorf(r.x), c0 = ceilf(r.x);
    float wf0 = 1.0f - (r.x - f0), wc0 = 1.0f - (c0 - r.x);
    float f1 = floorf(r.y), c1 = ceilf(r.y);
    float wf1 = 1.0f - (r.y - f1), wc1 = 1.0f - (c1 - r.y);
    float f2 = floorf(r.z), c2 = ceilf(r.z);
    float wf2 = 1.0f - (r.z - f2), wc2 = 1.0f - (c2 - r.z);
    float f3 = floorf(r.w), c3 = ceilf(r.w);
    float wf3 = 1.0f - (r.w - f3), wc3 = 1.0f - (c3 - r.w);

    int if0 = (int)f0, ic0 = (int)c0;
    int if1 = (int)f1, ic1 = (int)c1;
    int if2 = (int)f2, ic2 = (int)c2;
    int if3 = (int)f3, ic3 = (int)c3;

    float xff, xfc, xcf, xcc;
    gather_pair(x + (long)if0 * DIM, if1, ic1, xff, xfc);
    gather_pair(x + (long)ic0 * DIM, if1, ic1, xcf, xcc);

    float G = wf0 * (wf1 * xff + wc1 * xfc)
            + wc0 * (wf1 * xcf + wc1 * xcc);
    float gv = G * v;

    scatter_pair(y + (long)if2 * DIM, if3, ic3, gv * wf2 * wf3, gv * wf2 * wc3);
    scatter_pair(y + (long)ic2 * DIM, if3, ic3, gv * wc2 * wf3, gv * wc2 * wc3);
}

__global__ void __launch_bounds__(256) hyper_main_kernel(
    const float* __restrict__ x,
    const float4* __restrict__ ri,   // [N] of (r0,r1,r2,r3)
    const float* __restrict__ rv,    // [N]
    float* __restrict__ y,
    int N, int T)                    // T = threads doing work; sample pair (tid, tid+T)
{
    int tid = blockIdx.x * blockDim.x + threadIdx.x;
    if (tid >= T) return;            // R10 fix: mask rounded-up grid overflow

    int n0 = tid;
    int n1 = tid + T;
    bool has1 = n1 < N;

    // Batch loads up front for MLP.
    float4 r0 = ri[n0];
    float  v0 = rv[n0];
    float4 r1;
    float  v1 = 0.f;
    if (has1) { r1 = ri[n1]; v1 = rv[n1]; }

    process_sample(x, r0, v0, y);
    if (has1) process_sample(x, r1, v1, y);
}

extern "C" void kernel_launch(void* const* d_in, const int* in_sizes, int n_in,
                              void* d_out, int out_size) {
    const float*  x  = (const float*)d_in[0];   // 1024*1024
    const float4* ri = (const float4*)d_in[1];  // N x float4
    const float*  rv = (const float*)d_in[2];   // N
    float*        y  = (float*)d_out;           // 1024*1024

    int N = in_sizes[2];

    int n4 = out_size / 4;
    hyper_zero_kernel<<<(n4 + 255) / 256, 256>>>((float4*)y, n4);

    int T = (N + 1) / 2;                 // 2 samples per thread
    int blocks = (T + 255) / 256;
    hyper_main_kernel<<<blocks, 256>>>(x, ri, rv, y, N, T);
}

// round 12
// speedup vs baseline: 1.0835x; 1.0167x over previous
#include <cuda_runtime.h>
#include <cuda_bf16.h>
#include <cstdint>

// HyperLayer multilinear gather/scatter, factorized:
//   G = bilinear gather from x over (dim0,dim1); y[o2,o3] += v*G*w2*w3 over 4 combos.
// L1tex-wavefront bound (divergent gathers + atomics). Fuse adjacent-column
// pairs into float2 ops when the floor col index is even; 2 samples/thread
// for MLP. R10 fix: guard on tid < T (overflow threads of the rounded-up grid
// were double-processing 112 samples).

#define DIM 1024

__global__ void hyper_zero_kernel(float4* __restrict__ y, int n4) {
    int i = blockIdx.x * blockDim.x + threadIdx.x;
    if (i < n4) y[i] = make_float4(0.f, 0.f, 0.f, 0.f);
}

// Gather x[base+i], x[base+j] where j==i or j==i+1 (floor/ceil of same coord).
__device__ __forceinline__ void gather_pair(const float* __restrict__ base,
                                            int i, int j, float& a, float& b) {
    if (((i & 1) == 0) && (j == i + 1)) {
        float2 p = __ldg((const float2*)(base + i));
        a = p.x; b = p.y;
    } else {
        a = __ldg(base + i);
        b = (j == i) ? a : __ldg(base + j);
    }
}

// Scatter-add va -> base[i], vb -> base[j] (j==i or j==i+1).
__device__ __forceinline__ void scatter_pair(float* __restrict__ base,
                                             int i, int j, float va, float vb) {
    if (((i & 1) == 0) && (j == i + 1)) {
        atomicAdd((float2*)(base + i), make_float2(va, vb));
    } else {
        // j==i case: two adds to the same address == reference double-count.
        atomicAdd(base + i, va);
        atomicAdd(base + j, vb);
    }
}

__device__ __forceinline__ void process_sample(const float* __restrict__ x,
                                               float4 r, float v,
                                               float* __restrict__ y) {
    // wf = 1-(r-floor), wc = 1-(ceil-r); matches reference including the
    // frac==0 double-count (floor==ceil, both weights 1).
    float f0 = floorf(r.x), c0 = ceilf(r.x);
    float wf0 = 1.0f - (r.x - f0), wc0 = 1.0f - (c0 - r.x);
    float f1 = floorf(r.y), c1 = ceilf(r.y);
    float wf1 = 1.0f - (r.y - f1), wc1 = 1.0f - (c1 - r.y);
    float f2 = floorf(r.z), c2 = ceilf(r.z);
    float wf2 = 1.0f - (r.z - f2), wc2 = 1.0f - (c2 - r.z);
    float f3 = floorf(r.w), c3 = ceilf(r.w);
    float wf3 = 1.0f - (r.w - f3), wc3 = 1.0f - (c3 - r.w);

    int if0 = (int)f0, ic0 = (int)c0;
    int if1 = (int)f1, ic1 = (int)c1;
    int if2 = (int)f2, ic2 = (int)c2;
    int if3 = (int)f3, ic3 = (int)c3;

    float xff, xfc, xcf, xcc;
    gather_pair(x + (long)if0 * DIM, if1, ic1, xff, xfc);
    gather_pair(x + (long)ic0 * DIM, if1, ic1, xcf, xcc);

    float G = wf0 * (wf1 * xff + wc1 * xfc)
            + wc0 * (wf1 * xcf + wc1 * xcc);
    float gv = G * v;

    scatter_pair(y + (long)if2 * DIM, if3, ic3, gv * wf2 * wf3, gv * wf2 * wc3);
    scatter_pair(y + (long)ic2 * DIM, if3, ic3, gv * wc2 * wf3, gv * wc2 * wc3);
}

__global__ void __launch_bounds__(256) hyper_main_kernel(
    const float* __restrict__ x,
    const float4* __restrict__ ri,   // [N] of (r0,r1,r2,r3)
    const float* __restrict__ rv,    // [N]
    float* __restrict__ y,
    int N, int T)                    // T = threads doing work; sample pair (tid, tid+T)
{
    int tid = blockIdx.x * blockDim.x + threadIdx.x;
    if (tid >= T) return;            // R10 fix: mask rounded-up grid overflow

    int n0 = tid;
    int n1 = tid + T;
    bool has1 = n1 < N;

    // Batch loads up front for MLP.
    float4 r0 = ri[n0];
    float  v0 = rv[n0];
    float4 r1;
    float  v1 = 0.f;
    if (has1) { r1 = ri[n1]; v1 = rv[n1]; }

    process_sample(x, r0, v0, y);
    if (has1) process_sample(x, r1, v1, y);
}

extern "C" void kernel_launch(void* const* d_in, const int* in_sizes, int n_in,
                              void* d_out, int out_size) {
    const float*  x  = (const float*)d_in[0];   // 1024*1024
    const float4* ri = (const float4*)d_in[1];  // N x float4
    const float*  rv = (const float*)d_in[2];   // N
    float*        y  = (float*)d_out;           // 1024*1024

    int N = in_sizes[2];

    int n4 = out_size / 4;
    hyper_zero_kernel<<<(n4 + 255) / 256, 256>>>((float4*)y, n4);

    int T = (N + 1) / 2;                 // 2 samples per thread
    int blocks = (T + 255) / 256;
    hyper_main_kernel<<<blocks, 256>>>(x, ri, rv, y, N, T);
}

// round 13
// speedup vs baseline: 1.0963x; 1.0118x over previous
#include <cuda_runtime.h>
#include <cuda_bf16.h>
#include <cstdint>

// HyperLayer multilinear gather/scatter, factorized:
//   G = bilinear gather from x over (dim0,dim1); y[o2,o3] += v*G*w2*w3 over 4 combos.
// L1tex-wavefront bound (divergent gathers + atomics). Fuse adjacent-column
// pairs into float2 ops when the floor col index is even; 2 samples/thread
// for MLP. R10 fix: guard on tid < T (overflow threads of the rounded-up grid
// were double-processing 112 samples).

#define DIM 1024

__global__ void hyper_zero_kernel(float4* __restrict__ y, int n4) {
    int i = blockIdx.x * blockDim.x + threadIdx.x;
    if (i < n4) y[i] = make_float4(0.f, 0.f, 0.f, 0.f);
}

// Gather x[base+i], x[base+j] where j==i or j==i+1 (floor/ceil of same coord).
__device__ __forceinline__ void gather_pair(const float* __restrict__ base,
                                            int i, int j, float& a, float& b) {
    if (((i & 1) == 0) && (j == i + 1)) {
        float2 p = __ldg((const float2*)(base + i));
        a = p.x; b = p.y;
    } else {
        a = __ldg(base + i);
        b = (j == i) ? a : __ldg(base + j);
    }
}

// Scatter-add va -> base[i], vb -> base[j] (j==i or j==i+1).
__device__ __forceinline__ void scatter_pair(float* __restrict__ base,
                                             int i, int j, float va, float vb) {
    if (((i & 1) == 0) && (j == i + 1)) {
        atomicAdd((float2*)(base + i), make_float2(va, vb));
    } else {
        // j==i case: two adds to the same address == reference double-count.
        atomicAdd(base + i, va);
        atomicAdd(base + j, vb);
    }
}

__device__ __forceinline__ void process_sample(const float* __restrict__ x,
                                               float4 r, float v,
                                               float* __restrict__ y) {
    // wf = 1-(r-floor), wc = 1-(ceil-r); matches reference including the
    // frac==0 double-count (floor==ceil, both weights 1).
    float f0 = floorf(r.x), c0 = ceilf(r.x);
    float wf0 = 1.0f - (r.x - f0), wc0 = 1.0f - (c0 - r.x);
    float f1 = floorf(r.y), c1 = ceilf(r.y);
    float wf1 = 1.0f - (r.y - f1), wc1 = 1.0f - (c1 - r.y);
    float f2 = floorf(r.z), c2 = ceilf(r.z);
    float wf2 = 1.0f - (r.z - f2), wc2 = 1.0f - (c2 - r.z);
    float f3 = floorf(r.w), c3 = ceilf(r.w);
    float wf3 = 1.0f - (r.w - f3), wc3 = 1.0f - (c3 - r.w);

    int if0 = (int)f0, ic0 = (int)c0;
    int if1 = (int)f1, ic1 = (int)c1;
    int if2 = (int)f2, ic2 = (int)c2;
    int if3 = (int)f3, ic3 = (int)c3;

    float xff, xfc, xcf, xcc;
    gather_pair(x + (long)if0 * DIM, if1, ic1, xff, xfc);
    gather_pair(x + (long)ic0 * DIM, if1, ic1, xcf, xcc);

    float G = wf0 * (wf1 * xff + wc1 * xfc)
            + wc0 * (wf1 * xcf + wc1 * xcc);
    float gv = G * v;

    scatter_pair(y + (long)if2 * DIM, if3, ic3, gv * wf2 * wf3, gv * wf2 * wc3);
    scatter_pair(y + (long)ic2 * DIM, if3, ic3, gv * wc2 * wf3, gv * wc2 * wc3);
}

__global__ void __launch_bounds__(256) hyper_main_kernel(
    const float* __restrict__ x,
    const float4* __restrict__ ri,   // [N] of (r0,r1,r2,r3)
    const float* __restrict__ rv,    // [N]
    float* __restrict__ y,
    int N, int T)                    // T = threads doing work; sample pair (tid, tid+T)
{
    int tid = blockIdx.x * blockDim.x + threadIdx.x;
    if (tid >= T) return;            // R10 fix: mask rounded-up grid overflow

    int n0 = tid;
    int n1 = tid + T;
    bool has1 = n1 < N;

    // Batch loads up front for MLP.
    float4 r0 = ri[n0];
    float  v0 = rv[n0];
    float4 r1;
    float  v1 = 0.f;
    if (has1) { r1 = ri[n1]; v1 = rv[n1]; }

    process_sample(x, r0, v0, y);
    if (has1) process_sample(x, r1, v1, y);
}

extern "C" void kernel_launch(void* const* d_in, const int* in_sizes, int n_in,
                              void* d_out, int out_size) {
    const float*  x  = (const float*)d_in[0];   // 1024*1024
    const float4* ri = (const float4*)d_in[1];  // N x float4
    const float*  rv = (const float*)d_in[2];   // N
    float*        y  = (float*)d_out;           // 1024*1024

    int N = in_sizes[2];

    int n4 = out_size / 4;
    hyper_zero_kernel<<<(n4 + 255) / 256, 256>>>((float4*)y, n4);

    int T = (N + 1) / 2;                 // 2 samples per thread
    int blocks = (T + 255) / 256;
    hyper_main_kernel<<<blocks, 256>>>(x, ri, rv, y, N, T);
}